// round 14
// baseline (speedup 1.0000x reference)
#include <cuda_runtime.h>
#include <cuda_fp16.h>

// VectorQuantizer, persistent 2-CTA/SM kernel: two-pass fp16 mma.sync with
// K-permuted operands, half2 score epilogue (HFMA2/HMIN2), pair-ballot
// collect, exact fp32 re-score from smem x; loss finished by last CTA.
// inputs [32,64,64,64] f32 NCHW, weight [512,64] f32.
// out[0..N*D) = fl(x + fl(q-x)) NCHW; out[N*D..) = 1.25*mean((q-x)^2).

#define KCODES  512
#define DDIM    64
#define HWSZ    4096
#define NTOT    131072
#define TILE_M  128
#define NTILES  (NTOT / TILE_M)   // 1024
#define GRIDN   296               // 2 CTAs per SM
#define NTHREADS 512
#define QCAP    1024

typedef unsigned int u32;
typedef unsigned long long u64;

__device__ float g_partials[GRIDN];
__device__ u32   g_done = 0;

// ---- smem layout (bytes) ----
#define BSTRIDE   520                    // u32 per k-pair row of codebook (conflict-free)
#define OFF_B     0                      // f16x2 codebook [32][520] = 66560 (persistent)
#define OFF_A     66560                  // fp32 x-tile [128][68] = 34816 (16B-aligned rows)
#define ASTRIDE   68
#define OFF_SWN   (OFF_A + 34816)        // 512 f32 = 2048 (persistent)
#define OFF_SWNH  (OFF_SWN + 2048)       // 256 u32 packed half2 norms = 1024 (persistent)
#define OFF_SX    (OFF_SWNH + 1024)      // 128 f32 = 512
#define OFF_KEY   (OFF_SX + 512)         // 128 u64 = 1024
#define OFF_BMH   (OFF_KEY + 1024)       // 128*4 f32 = 2048
#define OFF_QCNT  (OFF_BMH + 2048)       // 16
#define OFF_OVF   (OFF_QCNT + 16)        // 128
#define OFF_QUE   (OFF_OVF + 128)        // QCAP*4 = 4096
#define SMEM_TOTAL (OFF_QUE + QCAP * 4)  // 112272  (2 per SM < 227KB)

// ---- scalar helpers ----
__device__ __forceinline__ u32 h2pack(float lo, float hi) {
    u32 r; asm("cvt.rn.f16x2.f32 %0, %1, %2;" : "=r"(r) : "f"(hi), "f"(lo)); return r;
}
__device__ __forceinline__ u64 ffma2(u64 a, u64 b, u64 c) {
    u64 d; asm("fma.rn.f32x2 %0, %1, %2, %3;" : "=l"(d) : "l"(a), "l"(b), "l"(c)); return d;
}
__device__ __forceinline__ u64 fadd2(u64 a, u64 b) {
    u64 d; asm("add.rn.f32x2 %0, %1, %2;" : "=l"(d) : "l"(a), "l"(b)); return d;
}
__device__ __forceinline__ u64 pack2(float lo, float hi) {
    u64 d; asm("mov.b64 %0, {%1, %2};" : "=l"(d) : "f"(lo), "f"(hi)); return d;
}
__device__ __forceinline__ void unpack2(u64 v, float& lo, float& hi) {
    asm("mov.b64 {%0, %1}, %2;" : "=f"(lo), "=f"(hi) : "l"(v));
}

// f16 inputs, f16 accumulators (2 regs = 4 halves)
#define MMAH(c, a, b0, b1)                                                      \
    asm volatile("mma.sync.aligned.m16n8k16.row.col.f16.f16.f16.f16 "           \
                 "{%0,%1}, {%2,%3,%4,%5}, {%6,%7}, {%0,%1};"                    \
                 : "+r"((c)[0]), "+r"((c)[1])                                   \
                 : "r"((a)[0]), "r"((a)[1]), "r"((a)[2]), "r"((a)[3]),          \
                   "r"(b0), "r"(b1))

// exact fp32 score, bit-identical FP sequence to the round-2 passing pipeline;
// x read from smem row (values identical to gmem; logical c order).
__device__ __forceinline__ float exact_d_s(const float* __restrict__ xrow,
                                           const float* __restrict__ wrow,
                                           float sx, float swn_k) {
    u64 a0 = 0ull, a1 = 0ull, a2 = 0ull, a3 = 0ull;
    #pragma unroll
    for (int j = 0; j < DDIM / 2; j += 4) {
        u64 x0 = pack2(xrow[2*(j+0)], xrow[2*(j+0)+1]);
        u64 x1 = pack2(xrow[2*(j+1)], xrow[2*(j+1)+1]);
        u64 x2 = pack2(xrow[2*(j+2)], xrow[2*(j+2)+1]);
        u64 x3 = pack2(xrow[2*(j+3)], xrow[2*(j+3)+1]);
        u64 w0 = pack2(wrow[2*(j+0)], wrow[2*(j+0)+1]);
        u64 w1 = pack2(wrow[2*(j+1)], wrow[2*(j+1)+1]);
        u64 w2 = pack2(wrow[2*(j+2)], wrow[2*(j+2)+1]);
        u64 w3 = pack2(wrow[2*(j+3)], wrow[2*(j+3)+1]);
        a0 = ffma2(x0, w0, a0);
        a1 = ffma2(x1, w1, a1);
        a2 = ffma2(x2, w2, a2);
        a3 = ffma2(x3, w3, a3);
    }
    a0 = fadd2(a0, a1);
    a2 = fadd2(a2, a3);
    a0 = fadd2(a0, a2);
    float lo, hi;
    unpack2(a0, lo, hi);
    float dot = __fadd_rn(lo, hi);
    float t = __fadd_rn(sx, swn_k);
    return __fsub_rn(t, __fmul_rn(2.0f, dot));
}

extern __shared__ char smem[];

__global__ void __launch_bounds__(NTHREADS, 2)
vq_mma_kernel(const float* __restrict__ input,
              const float* __restrict__ weight,
              float* __restrict__ out, int out_size)
{
    u32*   Bp    = (u32*)(smem + OFF_B);
    float* A32   = (float*)(smem + OFF_A);
    float* SWN   = (float*)(smem + OFF_SWN);
    u32*   SWNH  = (u32*)(smem + OFF_SWNH);
    float* SX    = (float*)(smem + OFF_SX);
    u64*   KEY   = (u64*)(smem + OFF_KEY);
    float* BMH   = (float*)(smem + OFF_BMH);
    u32*   QCNT  = (u32*)(smem + OFF_QCNT);
    unsigned char* SOVF = (unsigned char*)(smem + OFF_OVF);
    u32*   QUE   = (u32*)(smem + OFF_QUE);

    const int tid = threadIdx.x;

    // ---- stage B ONCE with K-permutation pi + exact sequential norms ----
    {
        const int n = tid;
        const float4* wr = (const float4*)(weight + (size_t)n * DDIM);
        float s = 0.f;
        #pragma unroll
        for (int c4 = 0; c4 < DDIM / 4; c4++) {
            float4 wv = wr[c4];
            s = __fadd_rn(s, __fmul_rn(wv.x, wv.x));
            s = __fadd_rn(s, __fmul_rn(wv.y, wv.y));
            s = __fadd_rn(s, __fmul_rn(wv.z, wv.z));
            s = __fadd_rn(s, __fmul_rn(wv.w, wv.w));
            const int kb = c4 >> 2, t = c4 & 3;
            Bp[(8 * kb + t)     * BSTRIDE + n] = h2pack(wv.x, wv.y);
            Bp[(8 * kb + t + 4) * BSTRIDE + n] = h2pack(wv.z, wv.w);
        }
        SWN[n] = s;
    }
    __syncthreads();
    // packed half2 norms (pairs of adjacent codes)
    if (tid < KCODES / 2)
        SWNH[tid] = h2pack(SWN[2 * tid], SWN[2 * tid + 1]);

    // warp roles: 4 row-groups (32 rows) x 4 code-quarters (128 codes)
    const int lane  = tid & 31;
    const int g     = lane >> 2;
    const int tq    = lane & 3;
    const int w     = tid >> 5;
    const int rbase = (w >> 2) * 32;
    const int q     = w & 3;
    const int nb0   = q * 128;
    const unsigned FULL = 0xffffffffu;
    const __half2 c_m2 = __floats2half2_rn(-2.0f, -2.0f);
    const __half2 h_inf = __floats2half2_rn(6.0e4f, 6.0e4f);

    // staging/epilogue ownership: row = tid&127, c-part = tid>>7
    const int erow = tid & 127;
    const int ec0  = (tid >> 7) * 16;

    float lloss_acc = 0.f;
    __syncthreads();

    // ================= persistent tile loop =================
    for (int t = blockIdx.x; t < NTILES; t += GRIDN) {
        const int b   = t >> 5;
        const int hw0 = (t & 31) * TILE_M;
        const float* xbase = input + (size_t)b * DDIM * HWSZ + hw0;

        if (tid < TILE_M) { KEY[tid] = ~0ull; SOVF[tid] = 0; }
        if (tid == 0) *QCNT = 0;

        // ---- stage A coalesced LDG -> float4 STS ----
        {
            float4* arow4 = (float4*)(A32 + erow * ASTRIDE);
            #pragma unroll
            for (int i4 = 0; i4 < 4; i4++) {
                int c = ec0 + i4 * 4;
                float4 v;
                v.x = xbase[erow + (size_t)(c + 0) * HWSZ];
                v.y = xbase[erow + (size_t)(c + 1) * HWSZ];
                v.z = xbase[erow + (size_t)(c + 2) * HWSZ];
                v.w = xbase[erow + (size_t)(c + 3) * HWSZ];
                arow4[(ec0 >> 2) + i4] = v;
            }
        }
        __syncthreads();

        // ---- exact sequential sx via float4 (order x,y,z,w preserved) ----
        if (tid < TILE_M) {
            const float4* a4 = (const float4*)(A32 + tid * ASTRIDE);
            float sx = 0.f;
            #pragma unroll
            for (int c4 = 0; c4 < 16; c4++) {
                float4 v = a4[c4];
                sx = __fadd_rn(sx, __fmul_rn(v.x, v.x));
                sx = __fadd_rn(sx, __fmul_rn(v.y, v.y));
                sx = __fadd_rn(sx, __fmul_rn(v.z, v.z));
                sx = __fadd_rn(sx, __fmul_rn(v.w, v.w));
            }
            SX[tid] = sx;
        }

        // ---- A fragments (f16, pi-permuted): one float4 per (mt,ks,row-half) ----
        u32 afr[2][4][4];
        #pragma unroll
        for (int mt = 0; mt < 2; mt++) {
            const float4* r0 = (const float4*)(A32 + (rbase + mt * 16 + g) * ASTRIDE);
            const float4* r1 = (const float4*)(A32 + (rbase + mt * 16 + g + 8) * ASTRIDE);
            #pragma unroll
            for (int ks = 0; ks < 4; ks++) {
                float4 v0 = r0[ks * 4 + tq];
                float4 v1 = r1[ks * 4 + tq];
                afr[mt][ks][0] = h2pack(v0.x, v0.y);
                afr[mt][ks][1] = h2pack(v1.x, v1.y);
                afr[mt][ks][2] = h2pack(v0.z, v0.w);
                afr[mt][ks][3] = h2pack(v1.z, v1.w);
            }
        }
        __syncthreads();

        // ================= PASS 1: min only (half2 epilogue) =================
        __half2 bminh[4] = {h_inf, h_inf, h_inf, h_inf};

        #pragma unroll 1
        for (int n2 = 0; n2 < 8; n2++) {
            const int nb = nb0 + n2 * 16;
            u32 hacc[2][2][2];
            #pragma unroll
            for (int i = 0; i < 2; i++)
                #pragma unroll
                for (int j = 0; j < 2; j++) { hacc[i][j][0] = 0u; hacc[i][j][1] = 0u; }

            #pragma unroll
            for (int ks = 0; ks < 4; ks++) {
                const u32* p0 = Bp + (ks * 8 + tq) * BSTRIDE + nb + g;
                const u32* p1 = p0 + 4 * BSTRIDE;
                u32 b0a = p0[0], b0b = p0[8];
                u32 b1a = p1[0], b1b = p1[8];
                MMAH(hacc[0][0], afr[0][ks], b0a, b1a);
                MMAH(hacc[0][1], afr[0][ks], b0b, b1b);
                MMAH(hacc[1][0], afr[1][ks], b0a, b1a);
                MMAH(hacc[1][1], afr[1][ks], b0b, b1b);
            }

            __half2 swnh[2];
            swnh[0] = *(__half2*)&SWNH[(nb >> 1) + tq];
            swnh[1] = *(__half2*)&SWNH[((nb + 8) >> 1) + tq];

            #pragma unroll
            for (int mt = 0; mt < 2; mt++)
            #pragma unroll
            for (int nn = 0; nn < 2; nn++)
            #pragma unroll
            for (int ep = 0; ep < 2; ep++) {
                const int s = mt * 2 + ep;
                __half2 sv = __hfma2(*(__half2*)&hacc[mt][nn][ep], c_m2, swnh[nn]);
                bminh[s] = __hmin2(bminh[s], sv);
            }
        }

        // quad-merge mins; publish per (row, quarter)
        #pragma unroll
        for (int s = 0; s < 4; s++) {
            float bm = fminf(__low2float(bminh[s]), __high2float(bminh[s]));
            bm = fminf(bm, __shfl_xor_sync(FULL, bm, 1));
            bm = fminf(bm, __shfl_xor_sync(FULL, bm, 2));
            if (tq == 0) {
                int row = rbase + (s >> 1) * 16 + (s & 1) * 8 + g;
                BMH[row * 4 + q] = bm;
            }
        }
        __syncthreads();

        // thresholds (margin: f16 MMA err x2 + HFMA2 score rounding x2)
        float th[4];
        #pragma unroll
        for (int s = 0; s < 4; s++) {
            int row = rbase + (s >> 1) * 16 + (s & 1) * 8 + g;
            float bm = fminf(fminf(BMH[row * 4 + 0], BMH[row * 4 + 1]),
                             fminf(BMH[row * 4 + 2], BMH[row * 4 + 3]));
            th[s] = bm + fmaf(sqrtf(SX[row]), 1e-4f, 2.6e-3f);
        }

        // ================= PASS 2: bit-identical recompute + pair-ballot collect
        #pragma unroll 1
        for (int n2 = 0; n2 < 8; n2++) {
            const int nb = nb0 + n2 * 16;
            u32 hacc[2][2][2];
            #pragma unroll
            for (int i = 0; i < 2; i++)
                #pragma unroll
                for (int j = 0; j < 2; j++) { hacc[i][j][0] = 0u; hacc[i][j][1] = 0u; }

            #pragma unroll
            for (int ks = 0; ks < 4; ks++) {
                const u32* p0 = Bp + (ks * 8 + tq) * BSTRIDE + nb + g;
                const u32* p1 = p0 + 4 * BSTRIDE;
                u32 b0a = p0[0], b0b = p0[8];
                u32 b1a = p1[0], b1b = p1[8];
                MMAH(hacc[0][0], afr[0][ks], b0a, b1a);
                MMAH(hacc[0][1], afr[0][ks], b0b, b1b);
                MMAH(hacc[1][0], afr[1][ks], b0a, b1a);
                MMAH(hacc[1][1], afr[1][ks], b0b, b1b);
            }

            __half2 swnh[2];
            swnh[0] = *(__half2*)&SWNH[(nb >> 1) + tq];
            swnh[1] = *(__half2*)&SWNH[((nb + 8) >> 1) + tq];

            #pragma unroll
            for (int mt = 0; mt < 2; mt++)
            #pragma unroll
            for (int nn = 0; nn < 2; nn++)
            #pragma unroll
            for (int ep = 0; ep < 2; ep++) {
                const int s   = mt * 2 + ep;
                const int row = rbase + mt * 16 + ep * 8 + g;
                const int col = nb + nn * 8 + tq * 2;
                __half2 sv = __hfma2(*(__half2*)&hacc[mt][nn][ep], c_m2, swnh[nn]);
                float s0 = __low2float(sv);
                float s1 = __high2float(sv);
                bool tp = fminf(s0, s1) <= th[s];
                unsigned mp = __ballot_sync(FULL, tp);
                if (mp) {   // uniform branch (mp identical across warp)
                    #pragma unroll
                    for (int e = 0; e < 2; e++) {
                        bool take = ((e ? s1 : s0) <= th[s]);
                        unsigned m = __ballot_sync(FULL, take);
                        if (m) {
                            int leader = __ffs(m) - 1;
                            u32 base = 0;
                            if (lane == leader) base = atomicAdd(QCNT, (u32)__popc(m));
                            base = __shfl_sync(FULL, base, leader);
                            if (take) {
                                u32 pos = base + (u32)__popc(m & ((1u << lane) - 1u));
                                if (pos < QCAP) QUE[pos] = ((u32)row << 16) | (u32)(col + e);
                                else SOVF[row] = 1;
                            }
                        }
                    }
                }
            }
        }
        __syncthreads();

        // ---- exact rescore of queue (x from smem) ----
        {
            int qn = *QCNT;
            if (qn > QCAP) qn = QCAP;
            for (int i = tid; i < qn; i += NTHREADS) {
                u32 e = QUE[i];
                int row = e >> 16;
                int k   = e & 0xffff;
                float d = exact_d_s(A32 + row * ASTRIDE, weight + (size_t)k * DDIM,
                                    SX[row], SWN[k]);
                u64 key = ((u64)__float_as_uint(d) << 16) | (u64)k;
                atomicMin(&KEY[row], key);
            }
        }
        __syncthreads();

        // ---- epilogue: x from A32 (float4), codeword via float4 gather ----
        {
            int bidx;
            if (SOVF[erow]) {   // overflow fallback (never expected)
                float best = 3.4e38f; bidx = 0;
                for (int k = 0; k < KCODES; k++) {
                    float d = exact_d_s(A32 + erow * ASTRIDE, weight + (size_t)k * DDIM,
                                        SX[erow], SWN[k]);
                    if (d < best) { best = d; bidx = k; }
                }
            } else {
                bidx = (int)(KEY[erow] & 0xffffull);
            }

            const float4* q4 = (const float4*)(weight + (size_t)bidx * DDIM + ec0);
            const float4* a4 = (const float4*)(A32 + erow * ASTRIDE + ec0);
            float* outp = out + (size_t)b * DDIM * HWSZ + hw0 + erow;
            #pragma unroll
            for (int i4 = 0; i4 < 4; i4++) {
                float4 qv = q4[i4];
                float4 xv = a4[i4];
                const float qvv[4] = {qv.x, qv.y, qv.z, qv.w};
                const float xvv[4] = {xv.x, xv.y, xv.z, xv.w};
                #pragma unroll
                for (int j = 0; j < 4; j++) {
                    int i = i4 * 4 + j;
                    float e = __fsub_rn(qvv[j], xvv[j]);
                    outp[(size_t)(ec0 + i) * HWSZ] = __fadd_rn(xvv[j], e);
                    lloss_acc = fmaf(e, e, lloss_acc);
                }
            }
        }
        __syncthreads();   // A32/KEY/QCNT reuse safe for next tile
    }

    // ---- per-CTA loss reduction, then last CTA finishes ----
    {
        float* red = (float*)(smem + OFF_A);
        red[tid] = lloss_acc;
        __syncthreads();
        #pragma unroll
        for (int st = NTHREADS / 2; st > 0; st >>= 1) {
            if (tid < st) red[tid] += red[tid + st];
            __syncthreads();
        }
        __shared__ u32 s_last;
        if (tid == 0) {
            g_partials[blockIdx.x] = red[0];
            __threadfence();
            s_last = (atomicAdd(&g_done, 1u) == GRIDN - 1u) ? 1u : 0u;
        }
        __syncthreads();
        if (s_last && tid == 0) {
            float s = 0.f;
            for (int i = 0; i < GRIDN; i++) s += __ldcg(&g_partials[i]);
            float loss = s * 1.25f / (float)((long long)NTOT * DDIM);
            for (long long i = (long long)NTOT * DDIM; i < out_size; i++)
                out[i] = loss;
            atomicExch(&g_done, 0u);   // reset for next graph replay
        }
    }
}

extern "C" void kernel_launch(void* const* d_in, const int* in_sizes, int n_in,
                              void* d_out, int out_size)
{
    const float* input  = (const float*)d_in[0];
    const float* weight = (const float*)d_in[1];
    float* out = (float*)d_out;

    cudaFuncSetAttribute(vq_mma_kernel, cudaFuncAttributeMaxDynamicSharedMemorySize, SMEM_TOTAL);
    vq_mma_kernel<<<GRIDN, NTHREADS, SMEM_TOTAL>>>(input, weight, out, out_size);
}

// round 15
// speedup vs baseline: 1.0102x; 1.0102x over previous
#include <cuda_runtime.h>
#include <cuda_fp16.h>

// VectorQuantizer, persistent 2-CTA/SM kernel: two-pass fp16 mma.sync with
// K-permuted operand layout (float4 A-fragment loads), unroll-2 chunk loops
// for LDS/MMA overlap, ballot collect, exact fp32 re-score from smem x;
// loss finished by last CTA.
// inputs [32,64,64,64] f32 NCHW, weight [512,64] f32.
// out[0..N*D) = fl(x + fl(q-x)) NCHW; out[N*D..) = 1.25*mean((q-x)^2).

#define KCODES  512
#define DDIM    64
#define HWSZ    4096
#define NTOT    131072
#define TILE_M  128
#define NTILES  (NTOT / TILE_M)   // 1024
#define GRIDN   296               // 2 CTAs per SM
#define NTHREADS 512
#define QCAP    1024

typedef unsigned int u32;
typedef unsigned long long u64;

__device__ float g_partials[GRIDN];
__device__ u32   g_done = 0;

// ---- smem layout (bytes) ----
#define BSTRIDE   520                    // u32 per k-pair row of codebook (conflict-free)
#define OFF_B     0                      // f16x2 codebook [32][520] = 66560 (persistent)
#define OFF_A     66560                  // fp32 x-tile [128][68] = 34816 (16B-aligned rows)
#define ASTRIDE   68
#define OFF_SWN   (OFF_A + 34816)        // 512 f32 = 2048 (persistent)
#define OFF_SX    (OFF_SWN + 2048)       // 128 f32 = 512
#define OFF_KEY   (OFF_SX + 512)         // 128 u64 = 1024
#define OFF_BMH   (OFF_KEY + 1024)       // 128*4 f32 = 2048
#define OFF_QCNT  (OFF_BMH + 2048)       // 16
#define OFF_OVF   (OFF_QCNT + 16)        // 128
#define OFF_QUE   (OFF_OVF + 128)        // QCAP*4 = 4096
#define SMEM_TOTAL (OFF_QUE + QCAP * 4)  // 111248  (2 per SM < 227KB)

// ---- scalar helpers ----
__device__ __forceinline__ u32 h2pack(float lo, float hi) {
    u32 r; asm("cvt.rn.f16x2.f32 %0, %1, %2;" : "=r"(r) : "f"(hi), "f"(lo)); return r;
}
__device__ __forceinline__ u64 ffma2(u64 a, u64 b, u64 c) {
    u64 d; asm("fma.rn.f32x2 %0, %1, %2, %3;" : "=l"(d) : "l"(a), "l"(b), "l"(c)); return d;
}
__device__ __forceinline__ u64 fadd2(u64 a, u64 b) {
    u64 d; asm("add.rn.f32x2 %0, %1, %2;" : "=l"(d) : "l"(a), "l"(b)); return d;
}
__device__ __forceinline__ u64 pack2(float lo, float hi) {
    u64 d; asm("mov.b64 %0, {%1, %2};" : "=l"(d) : "f"(lo), "f"(hi)); return d;
}
__device__ __forceinline__ void unpack2(u64 v, float& lo, float& hi) {
    asm("mov.b64 {%0, %1}, %2;" : "=f"(lo), "=f"(hi) : "l"(v));
}

// f16 inputs, f16 accumulators (2 regs = 4 halves)
#define MMAH(c, a, b0, b1)                                                      \
    asm volatile("mma.sync.aligned.m16n8k16.row.col.f16.f16.f16.f16 "           \
                 "{%0,%1}, {%2,%3,%4,%5}, {%6,%7}, {%0,%1};"                    \
                 : "+r"((c)[0]), "+r"((c)[1])                                   \
                 : "r"((a)[0]), "r"((a)[1]), "r"((a)[2]), "r"((a)[3]),          \
                   "r"(b0), "r"(b1))

// exact fp32 score, bit-identical FP sequence to the round-2 passing pipeline;
// x read from smem row (values identical to gmem; logical c order).
__device__ __forceinline__ float exact_d_s(const float* __restrict__ xrow,
                                           const float* __restrict__ wrow,
                                           float sx, float swn_k) {
    u64 a0 = 0ull, a1 = 0ull, a2 = 0ull, a3 = 0ull;
    #pragma unroll
    for (int j = 0; j < DDIM / 2; j += 4) {
        u64 x0 = pack2(xrow[2*(j+0)], xrow[2*(j+0)+1]);
        u64 x1 = pack2(xrow[2*(j+1)], xrow[2*(j+1)+1]);
        u64 x2 = pack2(xrow[2*(j+2)], xrow[2*(j+2)+1]);
        u64 x3 = pack2(xrow[2*(j+3)], xrow[2*(j+3)+1]);
        u64 w0 = pack2(wrow[2*(j+0)], wrow[2*(j+0)+1]);
        u64 w1 = pack2(wrow[2*(j+1)], wrow[2*(j+1)+1]);
        u64 w2 = pack2(wrow[2*(j+2)], wrow[2*(j+2)+1]);
        u64 w3 = pack2(wrow[2*(j+3)], wrow[2*(j+3)+1]);
        a0 = ffma2(x0, w0, a0);
        a1 = ffma2(x1, w1, a1);
        a2 = ffma2(x2, w2, a2);
        a3 = ffma2(x3, w3, a3);
    }
    a0 = fadd2(a0, a1);
    a2 = fadd2(a2, a3);
    a0 = fadd2(a0, a2);
    float lo, hi;
    unpack2(a0, lo, hi);
    float dot = __fadd_rn(lo, hi);
    float t = __fadd_rn(sx, swn_k);
    return __fsub_rn(t, __fmul_rn(2.0f, dot));
}

extern __shared__ char smem[];

__global__ void __launch_bounds__(NTHREADS, 2)
vq_mma_kernel(const float* __restrict__ input,
              const float* __restrict__ weight,
              float* __restrict__ out, int out_size)
{
    u32*   Bp    = (u32*)(smem + OFF_B);
    float* A32   = (float*)(smem + OFF_A);
    float* SWN   = (float*)(smem + OFF_SWN);
    float* SX    = (float*)(smem + OFF_SX);
    u64*   KEY   = (u64*)(smem + OFF_KEY);
    float* BMH   = (float*)(smem + OFF_BMH);
    u32*   QCNT  = (u32*)(smem + OFF_QCNT);
    unsigned char* SOVF = (unsigned char*)(smem + OFF_OVF);
    u32*   QUE   = (u32*)(smem + OFF_QUE);

    const int tid = threadIdx.x;

    // ---- stage B ONCE with K-permutation pi + exact sequential norms ----
    {
        const int n = tid;
        const float4* wr = (const float4*)(weight + (size_t)n * DDIM);
        float s = 0.f;
        #pragma unroll
        for (int c4 = 0; c4 < DDIM / 4; c4++) {
            float4 wv = wr[c4];
            s = __fadd_rn(s, __fmul_rn(wv.x, wv.x));
            s = __fadd_rn(s, __fmul_rn(wv.y, wv.y));
            s = __fadd_rn(s, __fmul_rn(wv.z, wv.z));
            s = __fadd_rn(s, __fmul_rn(wv.w, wv.w));
            const int kb = c4 >> 2, t = c4 & 3;
            Bp[(8 * kb + t)     * BSTRIDE + n] = h2pack(wv.x, wv.y);
            Bp[(8 * kb + t + 4) * BSTRIDE + n] = h2pack(wv.z, wv.w);
        }
        SWN[n] = s;
    }

    // warp roles: 4 row-groups (32 rows) x 4 code-quarters (128 codes)
    const int lane  = tid & 31;
    const int g     = lane >> 2;
    const int tq    = lane & 3;
    const int w     = tid >> 5;
    const int rbase = (w >> 2) * 32;
    const int q     = w & 3;
    const int nb0   = q * 128;
    const unsigned FULL = 0xffffffffu;

    // staging/epilogue ownership: row = tid&127, c-part = tid>>7
    const int erow = tid & 127;
    const int ec0  = (tid >> 7) * 16;

    float lloss_acc = 0.f;
    __syncthreads();

    // ================= persistent tile loop =================
    for (int t = blockIdx.x; t < NTILES; t += GRIDN) {
        const int b   = t >> 5;
        const int hw0 = (t & 31) * TILE_M;
        const float* xbase = input + (size_t)b * DDIM * HWSZ + hw0;

        if (tid < TILE_M) { KEY[tid] = ~0ull; SOVF[tid] = 0; }
        if (tid == 0) *QCNT = 0;

        // ---- stage A coalesced LDG -> float4 STS ----
        {
            float4* arow4 = (float4*)(A32 + erow * ASTRIDE);
            #pragma unroll
            for (int i4 = 0; i4 < 4; i4++) {
                int c = ec0 + i4 * 4;
                float4 v;
                v.x = xbase[erow + (size_t)(c + 0) * HWSZ];
                v.y = xbase[erow + (size_t)(c + 1) * HWSZ];
                v.z = xbase[erow + (size_t)(c + 2) * HWSZ];
                v.w = xbase[erow + (size_t)(c + 3) * HWSZ];
                arow4[(ec0 >> 2) + i4] = v;
            }
        }
        __syncthreads();

        // ---- exact sequential sx via float4 (order x,y,z,w preserved) ----
        if (tid < TILE_M) {
            const float4* a4 = (const float4*)(A32 + tid * ASTRIDE);
            float sx = 0.f;
            #pragma unroll
            for (int c4 = 0; c4 < 16; c4++) {
                float4 v = a4[c4];
                sx = __fadd_rn(sx, __fmul_rn(v.x, v.x));
                sx = __fadd_rn(sx, __fmul_rn(v.y, v.y));
                sx = __fadd_rn(sx, __fmul_rn(v.z, v.z));
                sx = __fadd_rn(sx, __fmul_rn(v.w, v.w));
            }
            SX[tid] = sx;
        }

        // ---- A fragments (f16, pi-permuted): one float4 per (mt,ks,row-half) ----
        u32 afr[2][4][4];
        #pragma unroll
        for (int mt = 0; mt < 2; mt++) {
            const float4* r0 = (const float4*)(A32 + (rbase + mt * 16 + g) * ASTRIDE);
            const float4* r1 = (const float4*)(A32 + (rbase + mt * 16 + g + 8) * ASTRIDE);
            #pragma unroll
            for (int ks = 0; ks < 4; ks++) {
                float4 v0 = r0[ks * 4 + tq];
                float4 v1 = r1[ks * 4 + tq];
                afr[mt][ks][0] = h2pack(v0.x, v0.y);
                afr[mt][ks][1] = h2pack(v1.x, v1.y);
                afr[mt][ks][2] = h2pack(v0.z, v0.w);
                afr[mt][ks][3] = h2pack(v1.z, v1.w);
            }
        }
        __syncthreads();

        // ================= PASS 1: min only (unroll 2 for LDS/MMA overlap) ====
        float bmin[4] = {3.4e38f, 3.4e38f, 3.4e38f, 3.4e38f};

        #pragma unroll 2
        for (int n2 = 0; n2 < 8; n2++) {
            const int nb = nb0 + n2 * 16;
            // hoist swnc + B loads to chunk top (independent of MMA chain)
            float swnc[2][2];
            swnc[0][0] = SWN[nb + tq * 2];
            swnc[0][1] = SWN[nb + tq * 2 + 1];
            swnc[1][0] = SWN[nb + 8 + tq * 2];
            swnc[1][1] = SWN[nb + 8 + tq * 2 + 1];

            u32 bb[4][4];
            #pragma unroll
            for (int ks = 0; ks < 4; ks++) {
                const u32* p0 = Bp + (ks * 8 + tq) * BSTRIDE + nb + g;
                const u32* p1 = p0 + 4 * BSTRIDE;
                bb[ks][0] = p0[0]; bb[ks][1] = p0[8];
                bb[ks][2] = p1[0]; bb[ks][3] = p1[8];
            }

            u32 hacc[2][2][2];
            #pragma unroll
            for (int i = 0; i < 2; i++)
                #pragma unroll
                for (int j = 0; j < 2; j++) { hacc[i][j][0] = 0u; hacc[i][j][1] = 0u; }

            #pragma unroll
            for (int ks = 0; ks < 4; ks++) {
                MMAH(hacc[0][0], afr[0][ks], bb[ks][0], bb[ks][2]);
                MMAH(hacc[0][1], afr[0][ks], bb[ks][1], bb[ks][3]);
                MMAH(hacc[1][0], afr[1][ks], bb[ks][0], bb[ks][2]);
                MMAH(hacc[1][1], afr[1][ks], bb[ks][1], bb[ks][3]);
            }

            #pragma unroll
            for (int mt = 0; mt < 2; mt++)
            #pragma unroll
            for (int nn = 0; nn < 2; nn++)
            #pragma unroll
            for (int ep = 0; ep < 2; ep++) {
                const int s = mt * 2 + ep;
                float2 dd = __half22float2(*(__half2*)&hacc[mt][nn][ep]);
                float s0 = fmaf(-2.f, dd.x, swnc[nn][0]);
                float s1 = fmaf(-2.f, dd.y, swnc[nn][1]);
                bmin[s] = fminf(bmin[s], fminf(s0, s1));
            }
        }

        // quad-merge mins; publish per (row, quarter)
        #pragma unroll
        for (int s = 0; s < 4; s++) {
            float bm = bmin[s];
            bm = fminf(bm, __shfl_xor_sync(FULL, bm, 1));
            bm = fminf(bm, __shfl_xor_sync(FULL, bm, 2));
            if (tq == 0) {
                int row = rbase + (s >> 1) * 16 + (s & 1) * 8 + g;
                BMH[row * 4 + q] = bm;
            }
        }
        __syncthreads();

        // thresholds (margin: f16 input quant + f16 accum chain, x2 dots)
        float th[4];
        #pragma unroll
        for (int s = 0; s < 4; s++) {
            int row = rbase + (s >> 1) * 16 + (s & 1) * 8 + g;
            float bm = fminf(fminf(BMH[row * 4 + 0], BMH[row * 4 + 1]),
                             fminf(BMH[row * 4 + 2], BMH[row * 4 + 3]));
            th[s] = bm + fmaf(sqrtf(SX[row]), 1e-4f, 2e-3f);
        }

        // ================= PASS 2: bit-identical recompute + collect =========
        #pragma unroll 2
        for (int n2 = 0; n2 < 8; n2++) {
            const int nb = nb0 + n2 * 16;
            float swnc[2][2];
            swnc[0][0] = SWN[nb + tq * 2];
            swnc[0][1] = SWN[nb + tq * 2 + 1];
            swnc[1][0] = SWN[nb + 8 + tq * 2];
            swnc[1][1] = SWN[nb + 8 + tq * 2 + 1];

            u32 bb[4][4];
            #pragma unroll
            for (int ks = 0; ks < 4; ks++) {
                const u32* p0 = Bp + (ks * 8 + tq) * BSTRIDE + nb + g;
                const u32* p1 = p0 + 4 * BSTRIDE;
                bb[ks][0] = p0[0]; bb[ks][1] = p0[8];
                bb[ks][2] = p1[0]; bb[ks][3] = p1[8];
            }

            u32 hacc[2][2][2];
            #pragma unroll
            for (int i = 0; i < 2; i++)
                #pragma unroll
                for (int j = 0; j < 2; j++) { hacc[i][j][0] = 0u; hacc[i][j][1] = 0u; }

            #pragma unroll
            for (int ks = 0; ks < 4; ks++) {
                MMAH(hacc[0][0], afr[0][ks], bb[ks][0], bb[ks][2]);
                MMAH(hacc[0][1], afr[0][ks], bb[ks][1], bb[ks][3]);
                MMAH(hacc[1][0], afr[1][ks], bb[ks][0], bb[ks][2]);
                MMAH(hacc[1][1], afr[1][ks], bb[ks][1], bb[ks][3]);
            }

            #pragma unroll
            for (int mt = 0; mt < 2; mt++)
            #pragma unroll
            for (int nn = 0; nn < 2; nn++)
            #pragma unroll
            for (int ep = 0; ep < 2; ep++) {
                const int s   = mt * 2 + ep;
                const int row = rbase + mt * 16 + ep * 8 + g;
                const int col = nb + nn * 8 + tq * 2;
                float2 dd = __half22float2(*(__half2*)&hacc[mt][nn][ep]);
                float s0 = fmaf(-2.f, dd.x, swnc[nn][0]);
                float s1 = fmaf(-2.f, dd.y, swnc[nn][1]);
                #pragma unroll
                for (int e = 0; e < 2; e++) {
                    bool take = ((e ? s1 : s0) <= th[s]);
                    unsigned m = __ballot_sync(FULL, take);
                    if (m) {
                        int leader = __ffs(m) - 1;
                        u32 base = 0;
                        if (lane == leader) base = atomicAdd(QCNT, (u32)__popc(m));
                        base = __shfl_sync(FULL, base, leader);
                        if (take) {
                            u32 pos = base + (u32)__popc(m & ((1u << lane) - 1u));
                            if (pos < QCAP) QUE[pos] = ((u32)row << 16) | (u32)(col + e);
                            else SOVF[row] = 1;
                        }
                    }
                }
            }
        }
        __syncthreads();

        // ---- exact rescore of queue (x from smem) ----
        {
            int qn = *QCNT;
            if (qn > QCAP) qn = QCAP;
            for (int i = tid; i < qn; i += NTHREADS) {
                u32 e = QUE[i];
                int row = e >> 16;
                int k   = e & 0xffff;
                float d = exact_d_s(A32 + row * ASTRIDE, weight + (size_t)k * DDIM,
                                    SX[row], SWN[k]);
                u64 key = ((u64)__float_as_uint(d) << 16) | (u64)k;
                atomicMin(&KEY[row], key);
            }
        }
        __syncthreads();

        // ---- epilogue: x from A32 (float4), codeword via float4 gather ----
        {
            int bidx;
            if (SOVF[erow]) {   // overflow fallback (never expected)
                float best = 3.4e38f; bidx = 0;
                for (int k = 0; k < KCODES; k++) {
                    float d = exact_d_s(A32 + erow * ASTRIDE, weight + (size_t)k * DDIM,
                                        SX[erow], SWN[k]);
                    if (d < best) { best = d; bidx = k; }
                }
            } else {
                bidx = (int)(KEY[erow] & 0xffffull);
            }

            const float4* q4 = (const float4*)(weight + (size_t)bidx * DDIM + ec0);
            const float4* a4 = (const float4*)(A32 + erow * ASTRIDE + ec0);
            float* outp = out + (size_t)b * DDIM * HWSZ + hw0 + erow;
            #pragma unroll
            for (int i4 = 0; i4 < 4; i4++) {
                float4 qv = q4[i4];
                float4 xv = a4[i4];
                const float qvv[4] = {qv.x, qv.y, qv.z, qv.w};
                const float xvv[4] = {xv.x, xv.y, xv.z, xv.w};
                #pragma unroll
                for (int j = 0; j < 4; j++) {
                    int i = i4 * 4 + j;
                    float e = __fsub_rn(qvv[j], xvv[j]);
                    outp[(size_t)(ec0 + i) * HWSZ] = __fadd_rn(xvv[j], e);
                    lloss_acc = fmaf(e, e, lloss_acc);
                }
            }
        }
        __syncthreads();   // A32/KEY/QCNT reuse safe for next tile
    }

    // ---- per-CTA loss reduction, then last CTA finishes ----
    {
        float* red = (float*)(smem + OFF_A);
        red[tid] = lloss_acc;
        __syncthreads();
        #pragma unroll
        for (int st = NTHREADS / 2; st > 0; st >>= 1) {
            if (tid < st) red[tid] += red[tid + st];
            __syncthreads();
        }
        __shared__ u32 s_last;
        if (tid == 0) {
            g_partials[blockIdx.x] = red[0];
            __threadfence();
            s_last = (atomicAdd(&g_done, 1u) == GRIDN - 1u) ? 1u : 0u;
        }
        __syncthreads();
        if (s_last && tid == 0) {
            float s = 0.f;
            for (int i = 0; i < GRIDN; i++) s += __ldcg(&g_partials[i]);
            float loss = s * 1.25f / (float)((long long)NTOT * DDIM);
            for (long long i = (long long)NTOT * DDIM; i < out_size; i++)
                out[i] = loss;
            atomicExch(&g_done, 0u);   // reset for next graph replay
        }
    }
}

extern "C" void kernel_launch(void* const* d_in, const int* in_sizes, int n_in,
                              void* d_out, int out_size)
{
    const float* input  = (const float*)d_in[0];
    const float* weight = (const float*)d_in[1];
    float* out = (float*)d_out;

    cudaFuncSetAttribute(vq_mma_kernel, cudaFuncAttributeMaxDynamicSharedMemorySize, SMEM_TOTAL);
    vq_mma_kernel<<<GRIDN, NTHREADS, SMEM_TOTAL>>>(input, weight, out, out_size);
}